// round 15
// baseline (speedup 1.0000x reference)
#include <cuda_runtime.h>
#include <cuda_fp16.h>
#include <cstdint>
#include <cstddef>

// Problem constants
#define B_   2
#define S_   2048
#define H_   16
#define D_   128
#define HID  2048
#define MTOT (B_*S_)   // 4096

// ---------------- scratch (device globals; no allocations allowed) ----------
__device__ __half g_q[(size_t)MTOT*HID];     // [B,H,S,D]
__device__ __half g_k[(size_t)MTOT*HID];     // [B,H,S,D]
__device__ __half g_vT[(size_t)MTOT*HID];    // [B,H,D,S]  (V transposed)
__device__ __half g_ctx[(size_t)MTOT*HID];   // [B,S,HID]
__device__ __half g_hs[(size_t)MTOT*HID];    // fp16 hidden_states
__device__ __half g_w4[(size_t)4*HID*HID];   // fp16 Wq|Wk|Wv|Wo

// ---------------- helpers ----------------------------------------------------
__device__ __forceinline__ uint32_t smem_u32(const void* p) {
    uint32_t a;
    asm("{ .reg .u64 t; cvta.to.shared.u64 t, %1; cvt.u32.u64 %0, t; }" : "=r"(a) : "l"(p));
    return a;
}

// m16n8k16 fp16 mma (row.col), fp32 accumulate
__device__ __forceinline__ void mma16(float* c, const unsigned* a, const unsigned* b) {
    asm volatile(
        "mma.sync.aligned.m16n8k16.row.col.f32.f16.f16.f32 "
        "{%0,%1,%2,%3}, {%4,%5,%6,%7}, {%8,%9}, {%0,%1,%2,%3};\n"
        : "+f"(c[0]), "+f"(c[1]), "+f"(c[2]), "+f"(c[3])
        : "r"(a[0]), "r"(a[1]), "r"(a[2]), "r"(a[3]), "r"(b[0]), "r"(b[1]));
}

// ldmatrix x4: four 8x8 b16 tiles (native fp16 fragments)
__device__ __forceinline__ void ldsm4(unsigned* r, uint32_t addr) {
    asm volatile("ldmatrix.sync.aligned.m8n8.x4.shared.b16 {%0,%1,%2,%3}, [%4];"
        : "=r"(r[0]), "=r"(r[1]), "=r"(r[2]), "=r"(r[3]) : "r"(addr));
}

__device__ __forceinline__ void cpasync16(uint32_t saddr, const void* gaddr) {
    asm volatile("cp.async.cg.shared.global [%0], [%1], 16;\n" :: "r"(saddr), "l"(gaddr));
}
#define CP_COMMIT() asm volatile("cp.async.commit_group;\n" ::: "memory")

__device__ __forceinline__ unsigned h2u(float x, float y) {
    __half2 t = __floats2half2_rn(x, y);
    return *reinterpret_cast<unsigned*>(&t);
}

// ============================================================================
// prepass: fp32 -> fp16 (RN) for hs and the 4 weight matrices
// ============================================================================
__global__ __launch_bounds__(256)
void round_pre(const float* __restrict__ hs, const float* __restrict__ Wq,
               const float* __restrict__ Wk, const float* __restrict__ Wv,
               const float* __restrict__ Wo)
{
    const int z = blockIdx.z;
    const float* src = (z == 0) ? hs : (z == 1) ? Wq : (z == 2) ? Wk : (z == 3) ? Wv : Wo;
    __half* dst = (z == 0) ? g_hs : g_w4 + (size_t)(z - 1) * HID * HID;
    const size_t n4 = ((z == 0) ? (size_t)MTOT * HID : (size_t)HID * HID) >> 2;
    const size_t stride = (size_t)gridDim.x * blockDim.x;
    for (size_t i = (size_t)blockIdx.x * blockDim.x + threadIdx.x; i < n4; i += stride) {
        float4 v = ((const float4*)src)[i];
        ((__half2*)dst)[2 * i]     = __floats2half2_rn(v.x, v.y);
        ((__half2*)dst)[2 * i + 1] = __floats2half2_rn(v.z, v.w);
    }
}

// ============================================================================
// GEMM: C[128x128 tile] = A[M,K=2048] @ W[N,K]^T  (+ epilogue), fp16 MMA
// 8 warps as (wm 0..3) x (wn 0..1): warp m32 x n64.
// K-chunk = 32 halves; 4-stage cp.async pipeline; one sync per chunk.
// MODE 0: quantum epilogue; z selects {Wq->g_q, Wk->g_k, Wv->g_vT(transposed)}
// MODE 1: plain bias epilogue, A = g_ctx, W = Wo, writes fp32 [M,HID] to outp
// ============================================================================
#define NSTAGE 4
#define NCHUNK 64
#define STG_B  20480                    // (128+128) rows * 80 B
#define GEMM_DSMEM (NSTAGE * STG_B)     // 81920

template <int MODE>
__global__ __launch_bounds__(256)
void tgemm_k(const float* __restrict__ b0, const float* __restrict__ b1, const float* __restrict__ b2,
             const float* __restrict__ re2, const float* __restrict__ im2, const float* __restrict__ mg2,
             const float* __restrict__ re01a, const float* __restrict__ im01a, const float* __restrict__ mg01a,
             const float* __restrict__ re01b, const float* __restrict__ im01b, const float* __restrict__ mg01b,
             float* __restrict__ outp)
{
    extern __shared__ __align__(16) float dsm[];

    const int tid  = threadIdx.x;
    const int lane = tid & 31;
    const int warp = tid >> 5;
    const int g    = lane >> 2;
    const int tig  = lane & 3;
    const int tj   = lane >> 3;
    const int lr   = lane & 7;
    const int wm   = warp >> 1;       // 0..3 : 32 M-rows
    const int wn   = warp & 1;        // 0..1 : 64 N-cols
    const int m0   = blockIdx.y * 128;
    const int n0   = blockIdx.x * 128;
    const int z    = blockIdx.z;

    const __half* A  = (MODE == 0) ? g_hs : g_ctx;
    const __half* Wp = g_w4 + (size_t)((MODE == 0) ? z : 3) * HID * HID;
    const float* bia = (z == 0) ? b0 : (z == 1) ? b1 : b2;

    const uint32_t uS = smem_u32(dsm);
    const uint32_t aBase = uS + (uint32_t)(wm * 32 + (tj & 1) * 8 + lr) * 80u + (uint32_t)(tj >> 1) * 16u;
    const uint32_t bBase = uS + 10240u + (uint32_t)(wn * 64 + (tj >> 1) * 8 + lr) * 80u + (uint32_t)(tj & 1) * 16u;

    float acc[2][8][4];
#pragma unroll
    for (int i = 0; i < 2; i++)
#pragma unroll
        for (int j = 0; j < 8; j++)
#pragma unroll
            for (int q = 0; q < 4; q++) acc[i][j][q] = 0.f;

    // per-chunk: 256 rows x 64B = 1024 x16B transfers, 4 per thread
#define ISSUE(c) do { \
    const int k0_ = (c) * 32; \
    const uint32_t db_ = uS + (uint32_t)((c) & 3) * STG_B; \
    _Pragma("unroll") \
    for (int i = 0; i < 4; i++) { \
        int idx = i * 256 + tid; \
        int mt_ = idx >> 9; \
        int rem = idx & 511; \
        int r_ = rem >> 2, sg_ = rem & 3; \
        const __half* sp_ = mt_ ? (Wp + (size_t)(n0 + r_) * HID + k0_ + sg_ * 8) \
                                : (A  + (size_t)(m0 + r_) * HID + k0_ + sg_ * 8); \
        cpasync16(db_ + (uint32_t)mt_ * 10240u + (uint32_t)r_ * 80u + (uint32_t)sg_ * 16u, sp_); \
    } \
    CP_COMMIT(); \
} while (0)

    ISSUE(0); ISSUE(1); ISSUE(2);

#pragma unroll 1
    for (int c = 0; c < NCHUNK; c++) {
        if (c <= NCHUNK - 3)      asm volatile("cp.async.wait_group 2;\n" ::: "memory");
        else if (c == NCHUNK - 2) asm volatile("cp.async.wait_group 1;\n" ::: "memory");
        else                      asm volatile("cp.async.wait_group 0;\n" ::: "memory");
        __syncthreads();
        if (c + 3 < NCHUNK) ISSUE(c + 3);

        const uint32_t so = (uint32_t)(c & 3) * STG_B;
#pragma unroll
        for (int ks = 0; ks < 2; ks++) {   // two k16 steps per 32-half chunk
            unsigned a[2][4], bq[4][4];
#pragma unroll
            for (int mt = 0; mt < 2; mt++)
                ldsm4(a[mt], aBase + so + (uint32_t)mt * 1280u + (uint32_t)ks * 32u);
#pragma unroll
            for (int np = 0; np < 4; np++)
                ldsm4(bq[np], bBase + so + (uint32_t)np * 1280u + (uint32_t)ks * 32u);
#pragma unroll
            for (int mt = 0; mt < 2; mt++)
#pragma unroll
                for (int ni = 0; ni < 8; ni++)
                    mma16(acc[mt][ni], a[mt], &bq[ni >> 1][(ni & 1) * 2]);
        }
    }
#undef ISSUE

    // ---------------- epilogue ----------------
    if (MODE == 1) {
#pragma unroll
        for (int ni = 0; ni < 8; ni++) {
            int nc = n0 + wn * 64 + ni * 8 + tig * 2;
            float bb0 = __ldg(bia + nc), bb1 = __ldg(bia + nc + 1);
#pragma unroll
            for (int mt = 0; mt < 2; mt++)
#pragma unroll
                for (int rh = 0; rh < 2; rh++) {
                    int m = m0 + wm * 32 + mt * 16 + rh * 8 + g;
                    float2 v = make_float2(acc[mt][ni][rh * 2] + bb0,
                                           acc[mt][ni][rh * 2 + 1] + bb1);
                    *(float2*)(outp + (size_t)m * HID + nc) = v;
                }
        }
    } else if (z < 2) {
        const float* re = z ? re01b : re01a;
        const float* im = z ? im01b : im01a;
        const float* mg = z ? mg01b : mg01a;
        __half* dst = z ? g_k : g_q;
        const int bb2 = m0 >> 11;
        const int hh  = n0 >> 7;
#pragma unroll
        for (int ni = 0; ni < 8; ni++) {
            int nc = n0 + wn * 64 + ni * 8 + tig * 2;
            float bv0 = __ldg(bia + nc), bv1 = __ldg(bia + nc + 1);
            float r0v = __ldg(re + nc), r1v = __ldg(re + nc + 1);
            float i0v = __ldg(im + nc), i1v = __ldg(im + nc + 1);
            float m0v = __ldg(mg + nc), m1v = __ldg(mg + nc + 1);
            float s0v = sqrtf(r0v * r0v + i0v * i0v) * fabsf(m0v);
            float s1v = sqrtf(r1v * r1v + i1v * i1v) * fabsf(m1v);
            int dd = nc & 127;
#pragma unroll
            for (int mt = 0; mt < 2; mt++)
#pragma unroll
                for (int rh = 0; rh < 2; rh++) {
                    int m = m0 + wm * 32 + mt * 16 + rh * 8 + g;
                    int ss = m & 2047;
                    __half2 v = __floats2half2_rn(
                        fabsf(acc[mt][ni][rh * 2] + bv0) * s0v,
                        fabsf(acc[mt][ni][rh * 2 + 1] + bv1) * s1v);
                    *(__half2*)(dst + (((size_t)(bb2 * H_ + hh)) * S_ + ss) * D_ + dd) = v;
                }
        }
    } else {
        // V: transposed store -> g_vT[b,h,d,s], via fp32 smem transpose, 2 halves.
        float* sT = dsm;                          // 64*132 = 8448 floats < 20480
        const int hh  = n0 >> 7;
        const int bb2 = m0 >> 11;
        const int s0  = m0 & 2047;
#pragma unroll 1
        for (int half = 0; half < 2; half++) {
            __syncthreads();
            if (wn == half) {
#pragma unroll
                for (int ni = 0; ni < 8; ni++) {
                    int nrel = ni * 8 + tig * 2;
                    int nc = n0 + half * 64 + nrel;
                    float bv0 = __ldg(bia + nc), bv1 = __ldg(bia + nc + 1);
                    float r0v = __ldg(re2 + nc), r1v = __ldg(re2 + nc + 1);
                    float i0v = __ldg(im2 + nc), i1v = __ldg(im2 + nc + 1);
                    float m0v = __ldg(mg2 + nc), m1v = __ldg(mg2 + nc + 1);
                    float s0v = sqrtf(r0v * r0v + i0v * i0v) * fabsf(m0v);
                    float s1v = sqrtf(r1v * r1v + i1v * i1v) * fabsf(m1v);
#pragma unroll
                    for (int mt = 0; mt < 2; mt++)
#pragma unroll
                        for (int rh = 0; rh < 2; rh++) {
                            int mr = wm * 32 + mt * 16 + rh * 8 + g;   // 0..127
                            sT[nrel * 132 + mr] = fabsf(acc[mt][ni][rh * 2] + bv0) * s0v;
                            sT[(nrel + 1) * 132 + mr] = fabsf(acc[mt][ni][rh * 2 + 1] + bv1) * s1v;
                        }
                }
            }
            __syncthreads();
            {
                int nr = tid >> 2;                 // 0..63 (d within half)
                int cq = tid & 3;                  // 32-float chunk of m
                const float* srow = sT + nr * 132 + cq * 32;
                __half* drow = g_vT + (((size_t)(bb2 * H_ + hh)) * D_ + half * 64 + nr) * S_
                               + s0 + cq * 32;
#pragma unroll
                for (int j = 0; j < 16; j++)
                    *(__half2*)(drow + j * 2) = __floats2half2_rn(srow[j * 2], srow[j * 2 + 1]);
            }
        }
    }
}

// ============================================================================
// flash attention (fp16 operands, fp32 softmax/accum): R12 structure, with the
// single change that P never round-trips smem — score C-fragments are repacked
// in registers as PV A-fragments (mapping proven correct in R13's run).
// grid (S/128, H, B), 256 threads, warp w owns q-rows [w*16, w*16+16).
// smem (halves): sQ[128][136] | sK[128][136] | sVt[128][136] | sBias[128] floats
// ============================================================================
#define ALD 136                       // halves per row (272 B: ldsm conflict-free)
#define ATTN_SMEM (3 * 128 * ALD * 2 + 128 * 4)

__global__ __launch_bounds__(256)
void attn_k(const float* __restrict__ mask, const float* __restrict__ ent)
{
    extern __shared__ __align__(16) char sm[];
    __half* sQ  = (__half*)sm;
    __half* sK  = sQ + 128 * ALD;
    __half* sVt = sK + 128 * ALD;    // [d][t]
    float* sBias = (float*)(sVt + 128 * ALD);

    const int tid  = threadIdx.x;
    const int lane = tid & 31;
    const int w    = tid >> 5;
    const int g    = lane >> 2;
    const int tig  = lane & 3;
    const int tj   = lane >> 3;
    const int lr   = lane & 7;
    const int qt = blockIdx.x, h = blockIdx.y, b = blockIdx.z;
    const int mrow = w * 16;
    const float SCALE = 0.08838834764831845f;  // 1/sqrt(128)

    const __half* qg  = g_q  + (((size_t)(b * H_ + h)) * S_ + qt * 128) * D_;
    const __half* kg  = g_k  + ((size_t)(b * H_ + h)) * S_ * D_;
    const __half* vtg = g_vT + ((size_t)(b * H_ + h)) * D_ * S_;

    const uint32_t uQ = smem_u32(sQ);
    const uint32_t uK = smem_u32(sK);
    const uint32_t uV = smem_u32(sVt);
    const uint32_t aQ = uQ + (uint32_t)(mrow + (tj & 1) * 8 + lr) * 272u + (uint32_t)(tj >> 1) * 16u;
    const uint32_t bK = uK + (uint32_t)((tj >> 1) * 8 + lr) * 272u + (uint32_t)(tj & 1) * 16u;
    const uint32_t bV = uV + (uint32_t)((tj >> 1) * 8 + lr) * 272u + (uint32_t)(tj & 1) * 16u;

    // load Q tile: 128 rows x 256B = 2048 x16B, 8 per thread
#pragma unroll
    for (int i = 0; i < 8; i++) {
        int idx = tid + i * 256;
        int r = idx >> 4, c16 = idx & 15;
        *(uint4*)(sQ + r * ALD + c16 * 8) = *(const uint4*)(qg + (size_t)r * D_ + c16 * 8);
    }

    float o[16][4];
#pragma unroll
    for (int i = 0; i < 16; i++)
#pragma unroll
        for (int j = 0; j < 4; j++) o[i][j] = 0.f;
    float m0s = -1e30f, m1s = -1e30f, l0 = 0.f, l1 = 0.f;

#pragma unroll 1
    for (int kt = 0; kt < 16; kt++) {
        __syncthreads();  // prev iter's sK/sVt readers done
        const int t0 = kt * 128;
        // K group
#pragma unroll
        for (int i = 0; i < 8; i++) {
            int idx = tid + i * 256;
            int r = idx >> 4, c16 = idx & 15;
            cpasync16(uK + (uint32_t)r * 272u + (uint32_t)c16 * 16u,
                      kg + (size_t)(t0 + r) * D_ + c16 * 8);
        }
        CP_COMMIT();
        // V group
#pragma unroll
        for (int i = 0; i < 8; i++) {
            int idx = tid + i * 256;
            int r = idx >> 4, c16 = idx & 15;
            cpasync16(uV + (uint32_t)r * 272u + (uint32_t)c16 * 16u,
                      vtg + (size_t)r * S_ + t0 + c16 * 8);
        }
        CP_COMMIT();
        if (tid < 128)
            sBias[tid] = __ldg(ent + h * H_ + (tid & 15)) + __ldg(mask + b * S_ + t0 + tid);
        asm volatile("cp.async.wait_group 1;\n" ::: "memory");   // K landed
        __syncthreads();

        // scores: S[16 x 128] = Q_warp @ K^T  (k-dim = D = 128, 8 k16 steps)
        float sc[16][4];
#pragma unroll
        for (int i = 0; i < 16; i++)
#pragma unroll
            for (int j = 0; j < 4; j++) sc[i][j] = 0.f;

#pragma unroll 2
        for (int ks = 0; ks < 8; ks++) {
            unsigned a[4], bq[8][4];
            ldsm4(a, aQ + (uint32_t)ks * 32u);
#pragma unroll
            for (int np = 0; np < 8; np++)
                ldsm4(bq[np], bK + (uint32_t)np * 4352u + (uint32_t)ks * 32u);
#pragma unroll
            for (int np = 0; np < 8; np++) {
                mma16(sc[np * 2],     a, &bq[np][0]);
                mma16(sc[np * 2 + 1], a, &bq[np][2]);
            }
        }

        // scale + bias + online softmax (rows g and g+8; stats shared in quad)
        float mx0 = -1e30f, mx1 = -1e30f;
#pragma unroll
        for (int ni = 0; ni < 16; ni++) {
            float b0v = sBias[ni * 8 + tig * 2];
            float b1v = sBias[ni * 8 + tig * 2 + 1];
            sc[ni][0] = sc[ni][0] * SCALE + b0v;
            sc[ni][1] = sc[ni][1] * SCALE + b1v;
            sc[ni][2] = sc[ni][2] * SCALE + b0v;
            sc[ni][3] = sc[ni][3] * SCALE + b1v;
            mx0 = fmaxf(mx0, fmaxf(sc[ni][0], sc[ni][1]));
            mx1 = fmaxf(mx1, fmaxf(sc[ni][2], sc[ni][3]));
        }
        mx0 = fmaxf(mx0, __shfl_xor_sync(0xffffffffu, mx0, 1));
        mx0 = fmaxf(mx0, __shfl_xor_sync(0xffffffffu, mx0, 2));
        mx1 = fmaxf(mx1, __shfl_xor_sync(0xffffffffu, mx1, 1));
        mx1 = fmaxf(mx1, __shfl_xor_sync(0xffffffffu, mx1, 2));
        const float nm0 = fmaxf(m0s, mx0), nm1 = fmaxf(m1s, mx1);
        const float al0 = __expf(m0s - nm0), al1 = __expf(m1s - nm1);
        m0s = nm0; m1s = nm1;
        float rs0 = 0.f, rs1 = 0.f;
#pragma unroll
        for (int ni = 0; ni < 16; ni++) {
            sc[ni][0] = __expf(sc[ni][0] - nm0);
            sc[ni][1] = __expf(sc[ni][1] - nm0);
            sc[ni][2] = __expf(sc[ni][2] - nm1);
            sc[ni][3] = __expf(sc[ni][3] - nm1);
            rs0 += sc[ni][0] + sc[ni][1];
            rs1 += sc[ni][2] + sc[ni][3];
        }
        rs0 += __shfl_xor_sync(0xffffffffu, rs0, 1);
        rs0 += __shfl_xor_sync(0xffffffffu, rs0, 2);
        rs1 += __shfl_xor_sync(0xffffffffu, rs1, 1);
        rs1 += __shfl_xor_sync(0xffffffffu, rs1, 2);
        l0 = l0 * al0 + rs0;
        l1 = l1 * al1 + rs1;
#pragma unroll
        for (int ni = 0; ni < 16; ni++) {
            o[ni][0] *= al0; o[ni][1] *= al0;
            o[ni][2] *= al1; o[ni][3] *= al1;
        }

        asm volatile("cp.async.wait_group 0;\n" ::: "memory");   // V landed
        __syncthreads();  // visibility of other threads' sVt cp.async writes

        // O += P @ V : P stays in registers (C-frag repacked as A-frag)
#pragma unroll 2
        for (int ks = 0; ks < 8; ks++) {
            unsigned pa[4];
            pa[0] = h2u(sc[2 * ks][0],     sc[2 * ks][1]);
            pa[1] = h2u(sc[2 * ks][2],     sc[2 * ks][3]);
            pa[2] = h2u(sc[2 * ks + 1][0], sc[2 * ks + 1][1]);
            pa[3] = h2u(sc[2 * ks + 1][2], sc[2 * ks + 1][3]);
            unsigned bq[8][4];
#pragma unroll
            for (int np = 0; np < 8; np++)
                ldsm4(bq[np], bV + (uint32_t)np * 4352u + (uint32_t)ks * 32u);
#pragma unroll
            for (int np = 0; np < 8; np++) {
                mma16(o[np * 2],     pa, &bq[np][0]);
                mma16(o[np * 2 + 1], pa, &bq[np][2]);
            }
        }
    }

    // epilogue: normalize + write ctx (fp16) in [B,S,HID] layout
    const float il0 = 1.f / l0, il1 = 1.f / l1;
    const int s0 = qt * 128 + mrow + g;
    const size_t base0 = ((size_t)(b * S_ + s0)) * HID + h * D_;
    const size_t base1 = base0 + (size_t)8 * HID;
#pragma unroll
    for (int ni = 0; ni < 16; ni++) {
        int d = ni * 8 + tig * 2;
        *(__half2*)(g_ctx + base0 + d) = __floats2half2_rn(o[ni][0] * il0, o[ni][1] * il0);
        *(__half2*)(g_ctx + base1 + d) = __floats2half2_rn(o[ni][2] * il1, o[ni][3] * il1);
    }
}

// ---------------- launch ------------------------------------------------------
extern "C" void kernel_launch(void* const* d_in, const int* in_sizes, int n_in,
                              void* d_out, int out_size)
{
    (void)in_sizes; (void)n_in; (void)out_size;
    const float* hs   = (const float*)d_in[0];
    const float* mask = (const float*)d_in[1];
    const float* q_re = (const float*)d_in[2];
    const float* q_im = (const float*)d_in[3];
    const float* q_mg = (const float*)d_in[5];
    const float* k_re = (const float*)d_in[6];
    const float* k_im = (const float*)d_in[7];
    const float* k_mg = (const float*)d_in[9];
    const float* v_re = (const float*)d_in[10];
    const float* v_im = (const float*)d_in[11];
    const float* v_mg = (const float*)d_in[13];
    const float* Wq = (const float*)d_in[14], *bq = (const float*)d_in[15];
    const float* Wk = (const float*)d_in[16], *bk = (const float*)d_in[17];
    const float* Wv = (const float*)d_in[18], *bv = (const float*)d_in[19];
    const float* Wo = (const float*)d_in[20], *bo = (const float*)d_in[21];
    const float* ent = (const float*)d_in[22];
    float* out = (float*)d_out;

    cudaFuncSetAttribute(tgemm_k<0>, cudaFuncAttributeMaxDynamicSharedMemorySize, GEMM_DSMEM);
    cudaFuncSetAttribute(tgemm_k<1>, cudaFuncAttributeMaxDynamicSharedMemorySize, GEMM_DSMEM);
    cudaFuncSetAttribute(attn_k, cudaFuncAttributeMaxDynamicSharedMemorySize, ATTN_SMEM);

    dim3 blk(256);

    round_pre<<<dim3(2048, 1, 5), blk>>>(hs, Wq, Wk, Wv, Wo);
    tgemm_k<0><<<dim3(16, 32, 3), blk, GEMM_DSMEM>>>(
        bq, bk, bv,
        v_re, v_im, v_mg,            // z==2 (V) quantum params
        q_re, q_im, q_mg,            // z==0 (Q)
        k_re, k_im, k_mg,            // z==1 (K)
        nullptr);
    attn_k<<<dim3(S_ / 128, H_, B_), blk, ATTN_SMEM>>>(mask, ent);
    tgemm_k<1><<<dim3(16, 32, 1), blk, GEMM_DSMEM>>>(
        bo, nullptr, nullptr,
        nullptr, nullptr, nullptr, nullptr, nullptr, nullptr,
        nullptr, nullptr, nullptr, out);
}

// round 16
// speedup vs baseline: 1.1100x; 1.1100x over previous
#include <cuda_runtime.h>
#include <cuda_fp16.h>
#include <cstdint>
#include <cstddef>

// Problem constants
#define B_   2
#define S_   2048
#define H_   16
#define D_   128
#define HID  2048
#define MTOT (B_*S_)   // 4096

// ---------------- scratch (device globals; no allocations allowed) ----------
__device__ __half g_q[(size_t)MTOT*HID];     // [B,H,S,D]
__device__ __half g_k[(size_t)MTOT*HID];     // [B,H,S,D]
__device__ __half g_vT[(size_t)MTOT*HID];    // [B,H,D,S]  (V transposed)
__device__ __half g_ctx[(size_t)MTOT*HID];   // [B,S,HID]
__device__ __half g_hs[(size_t)MTOT*HID];    // fp16 hidden_states
__device__ __half g_w4[(size_t)4*HID*HID];   // fp16 Wq|Wk|Wv|Wo

// ---------------- helpers ----------------------------------------------------
__device__ __forceinline__ uint32_t smem_u32(const void* p) {
    uint32_t a;
    asm("{ .reg .u64 t; cvta.to.shared.u64 t, %1; cvt.u32.u64 %0, t; }" : "=r"(a) : "l"(p));
    return a;
}

// m16n8k16 fp16 mma (row.col), fp32 accumulate
__device__ __forceinline__ void mma16(float* c, const unsigned* a, const unsigned* b) {
    asm volatile(
        "mma.sync.aligned.m16n8k16.row.col.f32.f16.f16.f32 "
        "{%0,%1,%2,%3}, {%4,%5,%6,%7}, {%8,%9}, {%0,%1,%2,%3};\n"
        : "+f"(c[0]), "+f"(c[1]), "+f"(c[2]), "+f"(c[3])
        : "r"(a[0]), "r"(a[1]), "r"(a[2]), "r"(a[3]), "r"(b[0]), "r"(b[1]));
}

// ldmatrix x4: four 8x8 b16 tiles (native fp16 fragments)
__device__ __forceinline__ void ldsm4(unsigned* r, uint32_t addr) {
    asm volatile("ldmatrix.sync.aligned.m8n8.x4.shared.b16 {%0,%1,%2,%3}, [%4];"
        : "=r"(r[0]), "=r"(r[1]), "=r"(r[2]), "=r"(r[3]) : "r"(addr));
}

__device__ __forceinline__ void cpasync16(uint32_t saddr, const void* gaddr) {
    asm volatile("cp.async.cg.shared.global [%0], [%1], 16;\n" :: "r"(saddr), "l"(gaddr));
}
#define CP_COMMIT() asm volatile("cp.async.commit_group;\n" ::: "memory")

// ============================================================================
// prepass: fp32 -> fp16 (RN) for hs and the 4 weight matrices
// ============================================================================
__global__ __launch_bounds__(256)
void round_pre(const float* __restrict__ hs, const float* __restrict__ Wq,
               const float* __restrict__ Wk, const float* __restrict__ Wv,
               const float* __restrict__ Wo)
{
    const int z = blockIdx.z;
    const float* src = (z == 0) ? hs : (z == 1) ? Wq : (z == 2) ? Wk : (z == 3) ? Wv : Wo;
    __half* dst = (z == 0) ? g_hs : g_w4 + (size_t)(z - 1) * HID * HID;
    const size_t n4 = ((z == 0) ? (size_t)MTOT * HID : (size_t)HID * HID) >> 2;
    const size_t stride = (size_t)gridDim.x * blockDim.x;
    for (size_t i = (size_t)blockIdx.x * blockDim.x + threadIdx.x; i < n4; i += stride) {
        float4 v = ((const float4*)src)[i];
        ((__half2*)dst)[2 * i]     = __floats2half2_rn(v.x, v.y);
        ((__half2*)dst)[2 * i + 1] = __floats2half2_rn(v.z, v.w);
    }
}

// ============================================================================
// GEMM: C[128x128 tile] = A[M,K=2048] @ W[N,K]^T  (+ epilogue), fp16 MMA
// 8 warps as (wm 0..3) x (wn 0..1): warp m32 x n64.
// K-chunk = 32 halves; 4-stage cp.async pipeline; one sync per chunk.
// MODE 0: quantum epilogue; z selects {Wq->g_q, Wk->g_k, Wv->g_vT(transposed)}
// MODE 1: plain bias epilogue, A = g_ctx, W = Wo, writes fp32 [M,HID] to outp
// ============================================================================
#define NSTAGE 4
#define NCHUNK 64
#define STG_B  20480                    // (128+128) rows * 80 B
#define GEMM_DSMEM (NSTAGE * STG_B)     // 81920

template <int MODE>
__global__ __launch_bounds__(256)
void tgemm_k(const float* __restrict__ b0, const float* __restrict__ b1, const float* __restrict__ b2,
             const float* __restrict__ re2, const float* __restrict__ im2, const float* __restrict__ mg2,
             const float* __restrict__ re01a, const float* __restrict__ im01a, const float* __restrict__ mg01a,
             const float* __restrict__ re01b, const float* __restrict__ im01b, const float* __restrict__ mg01b,
             float* __restrict__ outp)
{
    extern __shared__ __align__(16) float dsm[];

    const int tid  = threadIdx.x;
    const int lane = tid & 31;
    const int warp = tid >> 5;
    const int g    = lane >> 2;
    const int tig  = lane & 3;
    const int tj   = lane >> 3;
    const int lr   = lane & 7;
    const int wm   = warp >> 1;       // 0..3 : 32 M-rows
    const int wn   = warp & 1;        // 0..1 : 64 N-cols
    const int m0   = blockIdx.y * 128;
    const int n0   = blockIdx.x * 128;
    const int z    = blockIdx.z;

    const __half* A  = (MODE == 0) ? g_hs : g_ctx;
    const __half* Wp = g_w4 + (size_t)((MODE == 0) ? z : 3) * HID * HID;
    const float* bia = (z == 0) ? b0 : (z == 1) ? b1 : b2;

    const uint32_t uS = smem_u32(dsm);
    const uint32_t aBase = uS + (uint32_t)(wm * 32 + (tj & 1) * 8 + lr) * 80u + (uint32_t)(tj >> 1) * 16u;
    const uint32_t bBase = uS + 10240u + (uint32_t)(wn * 64 + (tj >> 1) * 8 + lr) * 80u + (uint32_t)(tj & 1) * 16u;

    float acc[2][8][4];
#pragma unroll
    for (int i = 0; i < 2; i++)
#pragma unroll
        for (int j = 0; j < 8; j++)
#pragma unroll
            for (int q = 0; q < 4; q++) acc[i][j][q] = 0.f;

    // per-chunk: 256 rows x 64B = 1024 x16B transfers, 4 per thread
#define ISSUE(c) do { \
    const int k0_ = (c) * 32; \
    const uint32_t db_ = uS + (uint32_t)((c) & 3) * STG_B; \
    _Pragma("unroll") \
    for (int i = 0; i < 4; i++) { \
        int idx = i * 256 + tid; \
        int mt_ = idx >> 9; \
        int rem = idx & 511; \
        int r_ = rem >> 2, sg_ = rem & 3; \
        const __half* sp_ = mt_ ? (Wp + (size_t)(n0 + r_) * HID + k0_ + sg_ * 8) \
                                : (A  + (size_t)(m0 + r_) * HID + k0_ + sg_ * 8); \
        cpasync16(db_ + (uint32_t)mt_ * 10240u + (uint32_t)r_ * 80u + (uint32_t)sg_ * 16u, sp_); \
    } \
    CP_COMMIT(); \
} while (0)

    ISSUE(0); ISSUE(1); ISSUE(2);

#pragma unroll 1
    for (int c = 0; c < NCHUNK; c++) {
        if (c <= NCHUNK - 3)      asm volatile("cp.async.wait_group 2;\n" ::: "memory");
        else if (c == NCHUNK - 2) asm volatile("cp.async.wait_group 1;\n" ::: "memory");
        else                      asm volatile("cp.async.wait_group 0;\n" ::: "memory");
        __syncthreads();
        if (c + 3 < NCHUNK) ISSUE(c + 3);

        const uint32_t so = (uint32_t)(c & 3) * STG_B;
#pragma unroll
        for (int ks = 0; ks < 2; ks++) {   // two k16 steps per 32-half chunk
            unsigned a[2][4], bq[4][4];
#pragma unroll
            for (int mt = 0; mt < 2; mt++)
                ldsm4(a[mt], aBase + so + (uint32_t)mt * 1280u + (uint32_t)ks * 32u);
#pragma unroll
            for (int np = 0; np < 4; np++)
                ldsm4(bq[np], bBase + so + (uint32_t)np * 1280u + (uint32_t)ks * 32u);
#pragma unroll
            for (int mt = 0; mt < 2; mt++)
#pragma unroll
                for (int ni = 0; ni < 8; ni++)
                    mma16(acc[mt][ni], a[mt], &bq[ni >> 1][(ni & 1) * 2]);
        }
    }
#undef ISSUE

    // ---------------- epilogue ----------------
    if (MODE == 1) {
#pragma unroll
        for (int ni = 0; ni < 8; ni++) {
            int nc = n0 + wn * 64 + ni * 8 + tig * 2;
            float bb0 = __ldg(bia + nc), bb1 = __ldg(bia + nc + 1);
#pragma unroll
            for (int mt = 0; mt < 2; mt++)
#pragma unroll
                for (int rh = 0; rh < 2; rh++) {
                    int m = m0 + wm * 32 + mt * 16 + rh * 8 + g;
                    float2 v = make_float2(acc[mt][ni][rh * 2] + bb0,
                                           acc[mt][ni][rh * 2 + 1] + bb1);
                    *(float2*)(outp + (size_t)m * HID + nc) = v;
                }
        }
    } else if (z < 2) {
        const float* re = z ? re01b : re01a;
        const float* im = z ? im01b : im01a;
        const float* mg = z ? mg01b : mg01a;
        __half* dst = z ? g_k : g_q;
        const int bb2 = m0 >> 11;
        const int hh  = n0 >> 7;
#pragma unroll
        for (int ni = 0; ni < 8; ni++) {
            int nc = n0 + wn * 64 + ni * 8 + tig * 2;
            float bv0 = __ldg(bia + nc), bv1 = __ldg(bia + nc + 1);
            float r0v = __ldg(re + nc), r1v = __ldg(re + nc + 1);
            float i0v = __ldg(im + nc), i1v = __ldg(im + nc + 1);
            float m0v = __ldg(mg + nc), m1v = __ldg(mg + nc + 1);
            float s0v = sqrtf(r0v * r0v + i0v * i0v) * fabsf(m0v);
            float s1v = sqrtf(r1v * r1v + i1v * i1v) * fabsf(m1v);
            int dd = nc & 127;
#pragma unroll
            for (int mt = 0; mt < 2; mt++)
#pragma unroll
                for (int rh = 0; rh < 2; rh++) {
                    int m = m0 + wm * 32 + mt * 16 + rh * 8 + g;
                    int ss = m & 2047;
                    __half2 v = __floats2half2_rn(
                        fabsf(acc[mt][ni][rh * 2] + bv0) * s0v,
                        fabsf(acc[mt][ni][rh * 2 + 1] + bv1) * s1v);
                    *(__half2*)(dst + (((size_t)(bb2 * H_ + hh)) * S_ + ss) * D_ + dd) = v;
                }
        }
    } else {
        // V: transposed store -> g_vT[b,h,d,s], via fp32 smem transpose, 2 halves.
        float* sT = dsm;                          // 64*132 = 8448 floats < 20480
        const int hh  = n0 >> 7;
        const int bb2 = m0 >> 11;
        const int s0  = m0 & 2047;
#pragma unroll 1
        for (int half = 0; half < 2; half++) {
            __syncthreads();
            if (wn == half) {
#pragma unroll
                for (int ni = 0; ni < 8; ni++) {
                    int nrel = ni * 8 + tig * 2;
                    int nc = n0 + half * 64 + nrel;
                    float bv0 = __ldg(bia + nc), bv1 = __ldg(bia + nc + 1);
                    float r0v = __ldg(re2 + nc), r1v = __ldg(re2 + nc + 1);
                    float i0v = __ldg(im2 + nc), i1v = __ldg(im2 + nc + 1);
                    float m0v = __ldg(mg2 + nc), m1v = __ldg(mg2 + nc + 1);
                    float s0v = sqrtf(r0v * r0v + i0v * i0v) * fabsf(m0v);
                    float s1v = sqrtf(r1v * r1v + i1v * i1v) * fabsf(m1v);
#pragma unroll
                    for (int mt = 0; mt < 2; mt++)
#pragma unroll
                        for (int rh = 0; rh < 2; rh++) {
                            int mr = wm * 32 + mt * 16 + rh * 8 + g;   // 0..127
                            sT[nrel * 132 + mr] = fabsf(acc[mt][ni][rh * 2] + bv0) * s0v;
                            sT[(nrel + 1) * 132 + mr] = fabsf(acc[mt][ni][rh * 2 + 1] + bv1) * s1v;
                        }
                }
            }
            __syncthreads();
            {
                int nr = tid >> 2;                 // 0..63 (d within half)
                int cq = tid & 3;                  // 32-float chunk of m
                const float* srow = sT + nr * 132 + cq * 32;
                __half* drow = g_vT + (((size_t)(bb2 * H_ + hh)) * D_ + half * 64 + nr) * S_
                               + s0 + cq * 32;
#pragma unroll
                for (int j = 0; j < 16; j++)
                    *(__half2*)(drow + j * 2) = __floats2half2_rn(srow[j * 2], srow[j * 2 + 1]);
            }
        }
    }
}

// ============================================================================
// flash attention (fp16 operands, fp32 softmax/accum), V pre-transposed,
// cp.async K/V in separate commit groups (V wait deferred behind softmax).
// P round-trips smem (proven faster than register repack: sc dies early).
// grid (S/128, H, B), 256 threads, warp w owns q-rows [w*16, w*16+16).
// smem (halves): sQ[128][136] | sK[128][136] (reused as P) | sVt[128][136]
//                | sBias[128] floats
// ============================================================================
#define ALD 136                       // halves per row (272 B: ldsm conflict-free)
#define ATTN_SMEM (3 * 128 * ALD * 2 + 128 * 4)

__global__ __launch_bounds__(256)
void attn_k(const float* __restrict__ mask, const float* __restrict__ ent)
{
    extern __shared__ __align__(16) char sm[];
    __half* sQ  = (__half*)sm;
    __half* sK  = sQ + 128 * ALD;    // holds P after scores
    __half* sVt = sK + 128 * ALD;    // [d][t]
    float* sBias = (float*)(sVt + 128 * ALD);

    const int tid  = threadIdx.x;
    const int lane = tid & 31;
    const int w    = tid >> 5;
    const int g    = lane >> 2;
    const int tig  = lane & 3;
    const int tj   = lane >> 3;
    const int lr   = lane & 7;
    const int qt = blockIdx.x, h = blockIdx.y, b = blockIdx.z;
    const int mrow = w * 16;
    const float SCALE = 0.08838834764831845f;  // 1/sqrt(128)

    const __half* qg  = g_q  + (((size_t)(b * H_ + h)) * S_ + qt * 128) * D_;
    const __half* kg  = g_k  + ((size_t)(b * H_ + h)) * S_ * D_;
    const __half* vtg = g_vT + ((size_t)(b * H_ + h)) * D_ * S_;

    const uint32_t uQ = smem_u32(sQ);
    const uint32_t uK = smem_u32(sK);
    const uint32_t uV = smem_u32(sVt);
    const uint32_t aQ = uQ + (uint32_t)(mrow + (tj & 1) * 8 + lr) * 272u + (uint32_t)(tj >> 1) * 16u;
    const uint32_t aP = uK + (uint32_t)(mrow + (tj & 1) * 8 + lr) * 272u + (uint32_t)(tj >> 1) * 16u;
    const uint32_t bK = uK + (uint32_t)((tj >> 1) * 8 + lr) * 272u + (uint32_t)(tj & 1) * 16u;
    const uint32_t bV = uV + (uint32_t)((tj >> 1) * 8 + lr) * 272u + (uint32_t)(tj & 1) * 16u;

    // load Q tile: 128 rows x 256B = 2048 x16B, 8 per thread
#pragma unroll
    for (int i = 0; i < 8; i++) {
        int idx = tid + i * 256;
        int r = idx >> 4, c16 = idx & 15;
        *(uint4*)(sQ + r * ALD + c16 * 8) = *(const uint4*)(qg + (size_t)r * D_ + c16 * 8);
    }

    float o[16][4];
#pragma unroll
    for (int i = 0; i < 16; i++)
#pragma unroll
        for (int j = 0; j < 4; j++) o[i][j] = 0.f;
    float m0s = -1e30f, m1s = -1e30f, l0 = 0.f, l1 = 0.f;

#pragma unroll 1
    for (int kt = 0; kt < 16; kt++) {
        __syncthreads();  // prev PV readers done; sK/sVt free
        const int t0 = kt * 128;
        // K group
#pragma unroll
        for (int i = 0; i < 8; i++) {
            int idx = tid + i * 256;
            int r = idx >> 4, c16 = idx & 15;
            cpasync16(uK + (uint32_t)r * 272u + (uint32_t)c16 * 16u,
                      kg + (size_t)(t0 + r) * D_ + c16 * 8);
        }
        CP_COMMIT();
        // V group
#pragma unroll
        for (int i = 0; i < 8; i++) {
            int idx = tid + i * 256;
            int r = idx >> 4, c16 = idx & 15;
            cpasync16(uV + (uint32_t)r * 272u + (uint32_t)c16 * 16u,
                      vtg + (size_t)r * S_ + t0 + c16 * 8);
        }
        CP_COMMIT();
        if (tid < 128)
            sBias[tid] = __ldg(ent + h * H_ + (tid & 15)) + __ldg(mask + b * S_ + t0 + tid);
        asm volatile("cp.async.wait_group 1;\n" ::: "memory");   // K landed
        __syncthreads();

        // scores: S[16 x 128] = Q_warp @ K^T  (k-dim = D = 128, 8 k16 steps)
        float sc[16][4];
#pragma unroll
        for (int i = 0; i < 16; i++)
#pragma unroll
            for (int j = 0; j < 4; j++) sc[i][j] = 0.f;

#pragma unroll 2
        for (int ks = 0; ks < 8; ks++) {
            unsigned a[4], bq[8][4];
            ldsm4(a, aQ + (uint32_t)ks * 32u);
#pragma unroll
            for (int np = 0; np < 8; np++)
                ldsm4(bq[np], bK + (uint32_t)np * 4352u + (uint32_t)ks * 32u);
#pragma unroll
            for (int np = 0; np < 8; np++) {
                mma16(sc[np * 2],     a, &bq[np][0]);
                mma16(sc[np * 2 + 1], a, &bq[np][2]);
            }
        }

        // scale + bias + online softmax (rows g and g+8; stats shared in quad)
        float mx0 = -1e30f, mx1 = -1e30f;
#pragma unroll
        for (int ni = 0; ni < 16; ni++) {
            float b0v = sBias[ni * 8 + tig * 2];
            float b1v = sBias[ni * 8 + tig * 2 + 1];
            sc[ni][0] = sc[ni][0] * SCALE + b0v;
            sc[ni][1] = sc[ni][1] * SCALE + b1v;
            sc[ni][2] = sc[ni][2] * SCALE + b0v;
            sc[ni][3] = sc[ni][3] * SCALE + b1v;
            mx0 = fmaxf(mx0, fmaxf(sc[ni][0], sc[ni][1]));
            mx1 = fmaxf(mx1, fmaxf(sc[ni][2], sc[ni][3]));
        }
        mx0 = fmaxf(mx0, __shfl_xor_sync(0xffffffffu, mx0, 1));
        mx0 = fmaxf(mx0, __shfl_xor_sync(0xffffffffu, mx0, 2));
        mx1 = fmaxf(mx1, __shfl_xor_sync(0xffffffffu, mx1, 1));
        mx1 = fmaxf(mx1, __shfl_xor_sync(0xffffffffu, mx1, 2));
        const float nm0 = fmaxf(m0s, mx0), nm1 = fmaxf(m1s, mx1);
        const float al0 = __expf(m0s - nm0), al1 = __expf(m1s - nm1);
        m0s = nm0; m1s = nm1;
        float rs0 = 0.f, rs1 = 0.f;
#pragma unroll
        for (int ni = 0; ni < 16; ni++) {
            sc[ni][0] = __expf(sc[ni][0] - nm0);
            sc[ni][1] = __expf(sc[ni][1] - nm0);
            sc[ni][2] = __expf(sc[ni][2] - nm1);
            sc[ni][3] = __expf(sc[ni][3] - nm1);
            rs0 += sc[ni][0] + sc[ni][1];
            rs1 += sc[ni][2] + sc[ni][3];
        }
        rs0 += __shfl_xor_sync(0xffffffffu, rs0, 1);
        rs0 += __shfl_xor_sync(0xffffffffu, rs0, 2);
        rs1 += __shfl_xor_sync(0xffffffffu, rs1, 1);
        rs1 += __shfl_xor_sync(0xffffffffu, rs1, 2);
        l0 = l0 * al0 + rs0;
        l1 = l1 * al1 + rs1;
#pragma unroll
        for (int ni = 0; ni < 16; ni++) {
            o[ni][0] *= al0; o[ni][1] *= al0;
            o[ni][2] *= al1; o[ni][3] *= al1;
        }

        asm volatile("cp.async.wait_group 0;\n" ::: "memory");   // V landed
        __syncthreads();  // all warps done reading sK -> safe to overwrite as P
#pragma unroll
        for (int ni = 0; ni < 16; ni++) {
            int c = ni * 8 + tig * 2;
            *(__half2*)(sK + (mrow + g    ) * ALD + c) = __floats2half2_rn(sc[ni][0], sc[ni][1]);
            *(__half2*)(sK + (mrow + g + 8) * ALD + c) = __floats2half2_rn(sc[ni][2], sc[ni][3]);
        }
        __syncthreads();

        // O += P @ V   (k-dim = 128 keys, 8 k16 steps; B = Vt[d][t])
#pragma unroll 2
        for (int ks = 0; ks < 8; ks++) {
            unsigned a[4], bq[8][4];
            ldsm4(a, aP + (uint32_t)ks * 32u);
#pragma unroll
            for (int np = 0; np < 8; np++)
                ldsm4(bq[np], bV + (uint32_t)np * 4352u + (uint32_t)ks * 32u);
#pragma unroll
            for (int np = 0; np < 8; np++) {
                mma16(o[np * 2],     a, &bq[np][0]);
                mma16(o[np * 2 + 1], a, &bq[np][2]);
            }
        }
    }

    // epilogue: normalize + write ctx (fp16) in [B,S,HID] layout
    const float il0 = 1.f / l0, il1 = 1.f / l1;
    const int s0 = qt * 128 + mrow + g;
    const size_t base0 = ((size_t)(b * S_ + s0)) * HID + h * D_;
    const size_t base1 = base0 + (size_t)8 * HID;
#pragma unroll
    for (int ni = 0; ni < 16; ni++) {
        int d = ni * 8 + tig * 2;
        *(__half2*)(g_ctx + base0 + d) = __floats2half2_rn(o[ni][0] * il0, o[ni][1] * il0);
        *(__half2*)(g_ctx + base1 + d) = __floats2half2_rn(o[ni][2] * il1, o[ni][3] * il1);
    }
}

// ---------------- launch ------------------------------------------------------
extern "C" void kernel_launch(void* const* d_in, const int* in_sizes, int n_in,
                              void* d_out, int out_size)
{
    (void)in_sizes; (void)n_in; (void)out_size;
    const float* hs   = (const float*)d_in[0];
    const float* mask = (const float*)d_in[1];
    const float* q_re = (const float*)d_in[2];
    const float* q_im = (const float*)d_in[3];
    const float* q_mg = (const float*)d_in[5];
    const float* k_re = (const float*)d_in[6];
    const float* k_im = (const float*)d_in[7];
    const float* k_mg = (const float*)d_in[9];
    const float* v_re = (const float*)d_in[10];
    const float* v_im = (const float*)d_in[11];
    const float* v_mg = (const float*)d_in[13];
    const float* Wq = (const float*)d_in[14], *bq = (const float*)d_in[15];
    const float* Wk = (const float*)d_in[16], *bk = (const float*)d_in[17];
    const float* Wv = (const float*)d_in[18], *bv = (const float*)d_in[19];
    const float* Wo = (const float*)d_in[20], *bo = (const float*)d_in[21];
    const float* ent = (const float*)d_in[22];
    float* out = (float*)d_out;

    cudaFuncSetAttribute(tgemm_k<0>, cudaFuncAttributeMaxDynamicSharedMemorySize, GEMM_DSMEM);
    cudaFuncSetAttribute(tgemm_k<1>, cudaFuncAttributeMaxDynamicSharedMemorySize, GEMM_DSMEM);
    cudaFuncSetAttribute(attn_k, cudaFuncAttributeMaxDynamicSharedMemorySize, ATTN_SMEM);

    dim3 blk(256);

    round_pre<<<dim3(2048, 1, 5), blk>>>(hs, Wq, Wk, Wv, Wo);
    tgemm_k<0><<<dim3(16, 32, 3), blk, GEMM_DSMEM>>>(
        bq, bk, bv,
        v_re, v_im, v_mg,            // z==2 (V) quantum params
        q_re, q_im, q_mg,            // z==0 (Q)
        k_re, k_im, k_mg,            // z==1 (K)
        nullptr);
    attn_k<<<dim3(S_ / 128, H_, B_), blk, ATTN_SMEM>>>(mask, ent);
    tgemm_k<1><<<dim3(16, 32, 1), blk, GEMM_DSMEM>>>(
        bo, nullptr, nullptr,
        nullptr, nullptr, nullptr, nullptr, nullptr, nullptr,
        nullptr, nullptr, nullptr, out);
}

// round 17
// speedup vs baseline: 1.1894x; 1.0716x over previous
#include <cuda_runtime.h>
#include <cuda_fp16.h>
#include <cstdint>
#include <cstddef>

// Problem constants
#define B_   2
#define S_   2048
#define H_   16
#define D_   128
#define HID  2048
#define MTOT (B_*S_)   // 4096

// ---------------- scratch (device globals; no allocations allowed) ----------
__device__ __half g_q[(size_t)MTOT*HID];     // [B,H,S,D]
__device__ __half g_k[(size_t)MTOT*HID];     // [B,H,S,D]
__device__ __half g_vT[(size_t)MTOT*HID];    // [B,H,D,S]  (V transposed)
__device__ __half g_ctx[(size_t)MTOT*HID];   // [B,S,HID]
__device__ __half g_hs[(size_t)MTOT*HID];    // fp16 hidden_states
__device__ __half g_w4[(size_t)4*HID*HID];   // fp16 Wq|Wk|Wv|Wo

// ---------------- helpers ----------------------------------------------------
__device__ __forceinline__ uint32_t smem_u32(const void* p) {
    uint32_t a;
    asm("{ .reg .u64 t; cvta.to.shared.u64 t, %1; cvt.u32.u64 %0, t; }" : "=r"(a) : "l"(p));
    return a;
}

// m16n8k16 fp16 mma (row.col), fp32 accumulate
__device__ __forceinline__ void mma16(float* c, const unsigned* a, const unsigned* b) {
    asm volatile(
        "mma.sync.aligned.m16n8k16.row.col.f32.f16.f16.f32 "
        "{%0,%1,%2,%3}, {%4,%5,%6,%7}, {%8,%9}, {%0,%1,%2,%3};\n"
        : "+f"(c[0]), "+f"(c[1]), "+f"(c[2]), "+f"(c[3])
        : "r"(a[0]), "r"(a[1]), "r"(a[2]), "r"(a[3]), "r"(b[0]), "r"(b[1]));
}

// ldmatrix x4: four 8x8 b16 tiles (native fp16 fragments)
__device__ __forceinline__ void ldsm4(unsigned* r, uint32_t addr) {
    asm volatile("ldmatrix.sync.aligned.m8n8.x4.shared.b16 {%0,%1,%2,%3}, [%4];"
        : "=r"(r[0]), "=r"(r[1]), "=r"(r[2]), "=r"(r[3]) : "r"(addr));
}

__device__ __forceinline__ void cpasync16(uint32_t saddr, const void* gaddr) {
    asm volatile("cp.async.cg.shared.global [%0], [%1], 16;\n" :: "r"(saddr), "l"(gaddr));
}
#define CP_COMMIT() asm volatile("cp.async.commit_group;\n" ::: "memory")

// ============================================================================
// prepass: fp32 -> fp16 (RN) for hs and the 4 weight matrices
// ============================================================================
__global__ __launch_bounds__(256)
void round_pre(const float* __restrict__ hs, const float* __restrict__ Wq,
               const float* __restrict__ Wk, const float* __restrict__ Wv,
               const float* __restrict__ Wo)
{
    const int z = blockIdx.z;
    const float* src = (z == 0) ? hs : (z == 1) ? Wq : (z == 2) ? Wk : (z == 3) ? Wv : Wo;
    __half* dst = (z == 0) ? g_hs : g_w4 + (size_t)(z - 1) * HID * HID;
    const size_t n4 = ((z == 0) ? (size_t)MTOT * HID : (size_t)HID * HID) >> 2;
    const size_t stride = (size_t)gridDim.x * blockDim.x;
    for (size_t i = (size_t)blockIdx.x * blockDim.x + threadIdx.x; i < n4; i += stride) {
        float4 v = ((const float4*)src)[i];
        ((__half2*)dst)[2 * i]     = __floats2half2_rn(v.x, v.y);
        ((__half2*)dst)[2 * i + 1] = __floats2half2_rn(v.z, v.w);
    }
}

// ============================================================================
// GEMM: C[128x128 tile] = A[M,K=2048] @ W[N,K]^T  (+ epilogue), fp16 MMA
// 8 warps as (wm 0..3) x (wn 0..1): warp m32 x n64.
// K-chunk = 64 halves (128B/row); 3-stage cp.async pipeline; ONE sync per
// chunk -> 32 barriers per CTA (was 64). Row stride 144B: ldsm conflict-free
// (144 mod 128 = 16 -> 8 rows cover 8 distinct 16B segments).
// MODE 0: quantum epilogue; z selects {Wq->g_q, Wk->g_k, Wv->g_vT(transposed)}
// MODE 1: plain bias epilogue, A = g_ctx, W = Wo, writes fp32 [M,HID] to outp
// ============================================================================
#define NSTAGE 3
#define NCHUNK 32                       // 2048 / 64
#define MAT_B  18432                    // 128 rows * 144 B
#define STG_B  (2 * MAT_B)              // 36864 (A | B)
#define GEMM_DSMEM (NSTAGE * STG_B)     // 110592

template <int MODE>
__global__ __launch_bounds__(256)
void tgemm_k(const float* __restrict__ b0, const float* __restrict__ b1, const float* __restrict__ b2,
             const float* __restrict__ re2, const float* __restrict__ im2, const float* __restrict__ mg2,
             const float* __restrict__ re01a, const float* __restrict__ im01a, const float* __restrict__ mg01a,
             const float* __restrict__ re01b, const float* __restrict__ im01b, const float* __restrict__ mg01b,
             float* __restrict__ outp)
{
    extern __shared__ __align__(16) float dsm[];

    const int tid  = threadIdx.x;
    const int lane = tid & 31;
    const int warp = tid >> 5;
    const int g    = lane >> 2;
    const int tig  = lane & 3;
    const int tj   = lane >> 3;
    const int lr   = lane & 7;
    const int wm   = warp >> 1;       // 0..3 : 32 M-rows
    const int wn   = warp & 1;        // 0..1 : 64 N-cols
    const int m0   = blockIdx.y * 128;
    const int n0   = blockIdx.x * 128;
    const int z    = blockIdx.z;

    const __half* A  = (MODE == 0) ? g_hs : g_ctx;
    const __half* Wp = g_w4 + (size_t)((MODE == 0) ? z : 3) * HID * HID;
    const float* bia = (z == 0) ? b0 : (z == 1) ? b1 : b2;

    const uint32_t uS = smem_u32(dsm);
    const uint32_t aBase = uS + (uint32_t)(wm * 32 + (tj & 1) * 8 + lr) * 144u + (uint32_t)(tj >> 1) * 16u;
    const uint32_t bBase = uS + MAT_B + (uint32_t)(wn * 64 + (tj >> 1) * 8 + lr) * 144u + (uint32_t)(tj & 1) * 16u;

    float acc[2][8][4];
#pragma unroll
    for (int i = 0; i < 2; i++)
#pragma unroll
        for (int j = 0; j < 8; j++)
#pragma unroll
            for (int q = 0; q < 4; q++) acc[i][j][q] = 0.f;

    // per-chunk: 256 rows x 128B = 2048 x16B transfers, 8 per thread
#define ISSUE(c) do { \
    const int k0_ = (c) * 64; \
    const uint32_t db_ = uS + (uint32_t)((c) % 3) * STG_B; \
    _Pragma("unroll") \
    for (int i = 0; i < 8; i++) { \
        int idx = i * 256 + tid; \
        int mt_ = idx >> 10; \
        int rem = idx & 1023; \
        int r_ = rem >> 3, sg_ = rem & 7; \
        const __half* sp_ = mt_ ? (Wp + (size_t)(n0 + r_) * HID + k0_ + sg_ * 8) \
                                : (A  + (size_t)(m0 + r_) * HID + k0_ + sg_ * 8); \
        cpasync16(db_ + (uint32_t)mt_ * MAT_B + (uint32_t)r_ * 144u + (uint32_t)sg_ * 16u, sp_); \
    } \
    CP_COMMIT(); \
} while (0)

    ISSUE(0); ISSUE(1);

#pragma unroll 1
    for (int c = 0; c < NCHUNK; c++) {
        if (c <= NCHUNK - 2) asm volatile("cp.async.wait_group 1;\n" ::: "memory");
        else                 asm volatile("cp.async.wait_group 0;\n" ::: "memory");
        __syncthreads();
        if (c + 2 < NCHUNK) ISSUE(c + 2);   // stage (c+2)%3 == (c-1)%3: freed by sync above

        const uint32_t so = (uint32_t)(c % 3) * STG_B;
#pragma unroll
        for (int ks = 0; ks < 4; ks++) {   // four k16 steps per 64-half chunk
            unsigned a[2][4], bq[4][4];
#pragma unroll
            for (int mt = 0; mt < 2; mt++)
                ldsm4(a[mt], aBase + so + (uint32_t)mt * 2304u + (uint32_t)ks * 32u);
#pragma unroll
            for (int np = 0; np < 4; np++)
                ldsm4(bq[np], bBase + so + (uint32_t)np * 2304u + (uint32_t)ks * 32u);
#pragma unroll
            for (int mt = 0; mt < 2; mt++)
#pragma unroll
                for (int ni = 0; ni < 8; ni++)
                    mma16(acc[mt][ni], a[mt], &bq[ni >> 1][(ni & 1) * 2]);
        }
    }
#undef ISSUE

    // ---------------- epilogue ----------------
    if (MODE == 1) {
#pragma unroll
        for (int ni = 0; ni < 8; ni++) {
            int nc = n0 + wn * 64 + ni * 8 + tig * 2;
            float bb0 = __ldg(bia + nc), bb1 = __ldg(bia + nc + 1);
#pragma unroll
            for (int mt = 0; mt < 2; mt++)
#pragma unroll
                for (int rh = 0; rh < 2; rh++) {
                    int m = m0 + wm * 32 + mt * 16 + rh * 8 + g;
                    float2 v = make_float2(acc[mt][ni][rh * 2] + bb0,
                                           acc[mt][ni][rh * 2 + 1] + bb1);
                    *(float2*)(outp + (size_t)m * HID + nc) = v;
                }
        }
    } else if (z < 2) {
        const float* re = z ? re01b : re01a;
        const float* im = z ? im01b : im01a;
        const float* mg = z ? mg01b : mg01a;
        __half* dst = z ? g_k : g_q;
        const int bb2 = m0 >> 11;
        const int hh  = n0 >> 7;
#pragma unroll
        for (int ni = 0; ni < 8; ni++) {
            int nc = n0 + wn * 64 + ni * 8 + tig * 2;
            float bv0 = __ldg(bia + nc), bv1 = __ldg(bia + nc + 1);
            float r0v = __ldg(re + nc), r1v = __ldg(re + nc + 1);
            float i0v = __ldg(im + nc), i1v = __ldg(im + nc + 1);
            float m0v = __ldg(mg + nc), m1v = __ldg(mg + nc + 1);
            float s0v = sqrtf(r0v * r0v + i0v * i0v) * fabsf(m0v);
            float s1v = sqrtf(r1v * r1v + i1v * i1v) * fabsf(m1v);
            int dd = nc & 127;
#pragma unroll
            for (int mt = 0; mt < 2; mt++)
#pragma unroll
                for (int rh = 0; rh < 2; rh++) {
                    int m = m0 + wm * 32 + mt * 16 + rh * 8 + g;
                    int ss = m & 2047;
                    __half2 v = __floats2half2_rn(
                        fabsf(acc[mt][ni][rh * 2] + bv0) * s0v,
                        fabsf(acc[mt][ni][rh * 2 + 1] + bv1) * s1v);
                    *(__half2*)(dst + (((size_t)(bb2 * H_ + hh)) * S_ + ss) * D_ + dd) = v;
                }
        }
    } else {
        // V: transposed store -> g_vT[b,h,d,s], via fp32 smem transpose, 2 halves.
        float* sT = dsm;                          // 64*132 = 8448 floats < 27648
        const int hh  = n0 >> 7;
        const int bb2 = m0 >> 11;
        const int s0  = m0 & 2047;
#pragma unroll 1
        for (int half = 0; half < 2; half++) {
            __syncthreads();
            if (wn == half) {
#pragma unroll
                for (int ni = 0; ni < 8; ni++) {
                    int nrel = ni * 8 + tig * 2;
                    int nc = n0 + half * 64 + nrel;
                    float bv0 = __ldg(bia + nc), bv1 = __ldg(bia + nc + 1);
                    float r0v = __ldg(re2 + nc), r1v = __ldg(re2 + nc + 1);
                    float i0v = __ldg(im2 + nc), i1v = __ldg(im2 + nc + 1);
                    float m0v = __ldg(mg2 + nc), m1v = __ldg(mg2 + nc + 1);
                    float s0v = sqrtf(r0v * r0v + i0v * i0v) * fabsf(m0v);
                    float s1v = sqrtf(r1v * r1v + i1v * i1v) * fabsf(m1v);
#pragma unroll
                    for (int mt = 0; mt < 2; mt++)
#pragma unroll
                        for (int rh = 0; rh < 2; rh++) {
                            int mr = wm * 32 + mt * 16 + rh * 8 + g;   // 0..127
                            sT[nrel * 132 + mr] = fabsf(acc[mt][ni][rh * 2] + bv0) * s0v;
                            sT[(nrel + 1) * 132 + mr] = fabsf(acc[mt][ni][rh * 2 + 1] + bv1) * s1v;
                        }
                }
            }
            __syncthreads();
            {
                int nr = tid >> 2;                 // 0..63 (d within half)
                int cq = tid & 3;                  // 32-float chunk of m
                const float* srow = sT + nr * 132 + cq * 32;
                __half* drow = g_vT + (((size_t)(bb2 * H_ + hh)) * D_ + half * 64 + nr) * S_
                               + s0 + cq * 32;
#pragma unroll
                for (int j = 0; j < 16; j++)
                    *(__half2*)(drow + j * 2) = __floats2half2_rn(srow[j * 2], srow[j * 2 + 1]);
            }
        }
    }
}

// ============================================================================
// flash attention (fp16 operands, fp32 softmax/accum), V pre-transposed,
// cp.async K/V in separate commit groups (V wait deferred behind softmax).
// P round-trips smem (proven faster than register repack: sc dies early).
// grid (S/128, H, B), 256 threads, warp w owns q-rows [w*16, w*16+16).
// smem (halves): sQ[128][136] | sK[128][136] (reused as P) | sVt[128][136]
//                | sBias[128] floats
// ============================================================================
#define ALD 136                       // halves per row (272 B: ldsm conflict-free)
#define ATTN_SMEM (3 * 128 * ALD * 2 + 128 * 4)

__global__ __launch_bounds__(256)
void attn_k(const float* __restrict__ mask, const float* __restrict__ ent)
{
    extern __shared__ __align__(16) char sm[];
    __half* sQ  = (__half*)sm;
    __half* sK  = sQ + 128 * ALD;    // holds P after scores
    __half* sVt = sK + 128 * ALD;    // [d][t]
    float* sBias = (float*)(sVt + 128 * ALD);

    const int tid  = threadIdx.x;
    const int lane = tid & 31;
    const int w    = tid >> 5;
    const int g    = lane >> 2;
    const int tig  = lane & 3;
    const int tj   = lane >> 3;
    const int lr   = lane & 7;
    const int qt = blockIdx.x, h = blockIdx.y, b = blockIdx.z;
    const int mrow = w * 16;
    const float SCALE = 0.08838834764831845f;  // 1/sqrt(128)

    const __half* qg  = g_q  + (((size_t)(b * H_ + h)) * S_ + qt * 128) * D_;
    const __half* kg  = g_k  + ((size_t)(b * H_ + h)) * S_ * D_;
    const __half* vtg = g_vT + ((size_t)(b * H_ + h)) * D_ * S_;

    const uint32_t uQ = smem_u32(sQ);
    const uint32_t uK = smem_u32(sK);
    const uint32_t uV = smem_u32(sVt);
    const uint32_t aQ = uQ + (uint32_t)(mrow + (tj & 1) * 8 + lr) * 272u + (uint32_t)(tj >> 1) * 16u;
    const uint32_t aP = uK + (uint32_t)(mrow + (tj & 1) * 8 + lr) * 272u + (uint32_t)(tj >> 1) * 16u;
    const uint32_t bK = uK + (uint32_t)((tj >> 1) * 8 + lr) * 272u + (uint32_t)(tj & 1) * 16u;
    const uint32_t bV = uV + (uint32_t)((tj >> 1) * 8 + lr) * 272u + (uint32_t)(tj & 1) * 16u;

    // load Q tile: 128 rows x 256B = 2048 x16B, 8 per thread
#pragma unroll
    for (int i = 0; i < 8; i++) {
        int idx = tid + i * 256;
        int r = idx >> 4, c16 = idx & 15;
        *(uint4*)(sQ + r * ALD + c16 * 8) = *(const uint4*)(qg + (size_t)r * D_ + c16 * 8);
    }

    float o[16][4];
#pragma unroll
    for (int i = 0; i < 16; i++)
#pragma unroll
        for (int j = 0; j < 4; j++) o[i][j] = 0.f;
    float m0s = -1e30f, m1s = -1e30f, l0 = 0.f, l1 = 0.f;

#pragma unroll 1
    for (int kt = 0; kt < 16; kt++) {
        __syncthreads();  // prev PV readers done; sK/sVt free
        const int t0 = kt * 128;
        // K group
#pragma unroll
        for (int i = 0; i < 8; i++) {
            int idx = tid + i * 256;
            int r = idx >> 4, c16 = idx & 15;
            cpasync16(uK + (uint32_t)r * 272u + (uint32_t)c16 * 16u,
                      kg + (size_t)(t0 + r) * D_ + c16 * 8);
        }
        CP_COMMIT();
        // V group
#pragma unroll
        for (int i = 0; i < 8; i++) {
            int idx = tid + i * 256;
            int r = idx >> 4, c16 = idx & 15;
            cpasync16(uV + (uint32_t)r * 272u + (uint32_t)c16 * 16u,
                      vtg + (size_t)r * S_ + t0 + c16 * 8);
        }
        CP_COMMIT();
        if (tid < 128)
            sBias[tid] = __ldg(ent + h * H_ + (tid & 15)) + __ldg(mask + b * S_ + t0 + tid);
        asm volatile("cp.async.wait_group 1;\n" ::: "memory");   // K landed
        __syncthreads();

        // scores: S[16 x 128] = Q_warp @ K^T  (k-dim = D = 128, 8 k16 steps)
        float sc[16][4];
#pragma unroll
        for (int i = 0; i < 16; i++)
#pragma unroll
            for (int j = 0; j < 4; j++) sc[i][j] = 0.f;

#pragma unroll 2
        for (int ks = 0; ks < 8; ks++) {
            unsigned a[4], bq[8][4];
            ldsm4(a, aQ + (uint32_t)ks * 32u);
#pragma unroll
            for (int np = 0; np < 8; np++)
                ldsm4(bq[np], bK + (uint32_t)np * 4352u + (uint32_t)ks * 32u);
#pragma unroll
            for (int np = 0; np < 8; np++) {
                mma16(sc[np * 2],     a, &bq[np][0]);
                mma16(sc[np * 2 + 1], a, &bq[np][2]);
            }
        }

        // scale + bias + online softmax (rows g and g+8; stats shared in quad)
        float mx0 = -1e30f, mx1 = -1e30f;
#pragma unroll
        for (int ni = 0; ni < 16; ni++) {
            float b0v = sBias[ni * 8 + tig * 2];
            float b1v = sBias[ni * 8 + tig * 2 + 1];
            sc[ni][0] = sc[ni][0] * SCALE + b0v;
            sc[ni][1] = sc[ni][1] * SCALE + b1v;
            sc[ni][2] = sc[ni][2] * SCALE + b0v;
            sc[ni][3] = sc[ni][3] * SCALE + b1v;
            mx0 = fmaxf(mx0, fmaxf(sc[ni][0], sc[ni][1]));
            mx1 = fmaxf(mx1, fmaxf(sc[ni][2], sc[ni][3]));
        }
        mx0 = fmaxf(mx0, __shfl_xor_sync(0xffffffffu, mx0, 1));
        mx0 = fmaxf(mx0, __shfl_xor_sync(0xffffffffu, mx0, 2));
        mx1 = fmaxf(mx1, __shfl_xor_sync(0xffffffffu, mx1, 1));
        mx1 = fmaxf(mx1, __shfl_xor_sync(0xffffffffu, mx1, 2));
        const float nm0 = fmaxf(m0s, mx0), nm1 = fmaxf(m1s, mx1);
        const float al0 = __expf(m0s - nm0), al1 = __expf(m1s - nm1);
        m0s = nm0; m1s = nm1;
        float rs0 = 0.f, rs1 = 0.f;
#pragma unroll
        for (int ni = 0; ni < 16; ni++) {
            sc[ni][0] = __expf(sc[ni][0] - nm0);
            sc[ni][1] = __expf(sc[ni][1] - nm0);
            sc[ni][2] = __expf(sc[ni][2] - nm1);
            sc[ni][3] = __expf(sc[ni][3] - nm1);
            rs0 += sc[ni][0] + sc[ni][1];
            rs1 += sc[ni][2] + sc[ni][3];
        }
        rs0 += __shfl_xor_sync(0xffffffffu, rs0, 1);
        rs0 += __shfl_xor_sync(0xffffffffu, rs0, 2);
        rs1 += __shfl_xor_sync(0xffffffffu, rs1, 1);
        rs1 += __shfl_xor_sync(0xffffffffu, rs1, 2);
        l0 = l0 * al0 + rs0;
        l1 = l1 * al1 + rs1;
#pragma unroll
        for (int ni = 0; ni < 16; ni++) {
            o[ni][0] *= al0; o[ni][1] *= al0;
            o[ni][2] *= al1; o[ni][3] *= al1;
        }

        asm volatile("cp.async.wait_group 0;\n" ::: "memory");   // V landed
        __syncthreads();  // all warps done reading sK -> safe to overwrite as P
#pragma unroll
        for (int ni = 0; ni < 16; ni++) {
            int c = ni * 8 + tig * 2;
            *(__half2*)(sK + (mrow + g    ) * ALD + c) = __floats2half2_rn(sc[ni][0], sc[ni][1]);
            *(__half2*)(sK + (mrow + g + 8) * ALD + c) = __floats2half2_rn(sc[ni][2], sc[ni][3]);
        }
        __syncthreads();

        // O += P @ V   (k-dim = 128 keys, 8 k16 steps; B = Vt[d][t])
#pragma unroll 2
        for (int ks = 0; ks < 8; ks++) {
            unsigned a[4], bq[8][4];
            ldsm4(a, aP + (uint32_t)ks * 32u);
#pragma unroll
            for (int np = 0; np < 8; np++)
                ldsm4(bq[np], bV + (uint32_t)np * 4352u + (uint32_t)ks * 32u);
#pragma unroll
            for (int np = 0; np < 8; np++) {
                mma16(o[np * 2],     a, &bq[np][0]);
                mma16(o[np * 2 + 1], a, &bq[np][2]);
            }
        }
    }

    // epilogue: normalize + write ctx (fp16) in [B,S,HID] layout
    const float il0 = 1.f / l0, il1 = 1.f / l1;
    const int s0 = qt * 128 + mrow + g;
    const size_t base0 = ((size_t)(b * S_ + s0)) * HID + h * D_;
    const size_t base1 = base0 + (size_t)8 * HID;
#pragma unroll
    for (int ni = 0; ni < 16; ni++) {
        int d = ni * 8 + tig * 2;
        *(__half2*)(g_ctx + base0 + d) = __floats2half2_rn(o[ni][0] * il0, o[ni][1] * il0);
        *(__half2*)(g_ctx + base1 + d) = __floats2half2_rn(o[ni][2] * il1, o[ni][3] * il1);
    }
}

// ---------------- launch ------------------------------------------------------
extern "C" void kernel_launch(void* const* d_in, const int* in_sizes, int n_in,
                              void* d_out, int out_size)
{
    (void)in_sizes; (void)n_in; (void)out_size;
    const float* hs   = (const float*)d_in[0];
    const float* mask = (const float*)d_in[1];
    const float* q_re = (const float*)d_in[2];
    const float* q_im = (const float*)d_in[3];
    const float* q_mg = (const float*)d_in[5];
    const float* k_re = (const float*)d_in[6];
    const float* k_im = (const float*)d_in[7];
    const float* k_mg = (const float*)d_in[9];
    const float* v_re = (const float*)d_in[10];
    const float* v_im = (const float*)d_in[11];
    const float* v_mg = (const float*)d_in[13];
    const float* Wq = (const float*)d_in[14], *bq = (const float*)d_in[15];
    const float* Wk = (const float*)d_in[16], *bk = (const float*)d_in[17];
    const float* Wv = (const float*)d_in[18], *bv = (const float*)d_in[19];
    const float* Wo = (const float*)d_in[20], *bo = (const float*)d_in[21];
    const float* ent = (const float*)d_in[22];
    float* out = (float*)d_out;

    cudaFuncSetAttribute(tgemm_k<0>, cudaFuncAttributeMaxDynamicSharedMemorySize, GEMM_DSMEM);
    cudaFuncSetAttribute(tgemm_k<1>, cudaFuncAttributeMaxDynamicSharedMemorySize, GEMM_DSMEM);
    cudaFuncSetAttribute(attn_k, cudaFuncAttributeMaxDynamicSharedMemorySize, ATTN_SMEM);

    dim3 blk(256);

    round_pre<<<dim3(2048, 1, 5), blk>>>(hs, Wq, Wk, Wv, Wo);
    tgemm_k<0><<<dim3(16, 32, 3), blk, GEMM_DSMEM>>>(
        bq, bk, bv,
        v_re, v_im, v_mg,            // z==2 (V) quantum params
        q_re, q_im, q_mg,            // z==0 (Q)
        k_re, k_im, k_mg,            // z==1 (K)
        nullptr);
    attn_k<<<dim3(S_ / 128, H_, B_), blk, ATTN_SMEM>>>(mask, ent);
    tgemm_k<1><<<dim3(16, 32, 1), blk, GEMM_DSMEM>>>(
        bo, nullptr, nullptr,
        nullptr, nullptr, nullptr, nullptr, nullptr, nullptr,
        nullptr, nullptr, nullptr, out);
}